// round 4
// baseline (speedup 1.0000x reference)
#include <cuda_runtime.h>

#define N_NODES 100000
#define N_EDGES 1600000
#define F_IN 48
#define F_HID 16
#define F_OUT 16

// Scratch (device globals — no allocation allowed).
// Y/Z: interleaved per-node tables, 32 floats (= 8 float4) per node:
//   float4 slots [0:4) = x @ W[0]  (a),  [4:8) = x @ W[1]  (b)
__device__ float4 g_Y[N_NODES * 8];
__device__ float4 g_Z[N_NODES * 8];
__device__ float4 g_AGG[N_NODES * 4];  // 16-float accumulator per node
__device__ float4 g_r1[N_NODES * 4];   // x @ root1 + b1
__device__ float4 g_r2[N_NODES * 4];   // h @ root2 + b2
__device__ int    g_cnt[N_NODES];      // in-degree (same both layers)
__device__ int    g_is64;              // 1 if edge_index is int64

__device__ __forceinline__ void red_add_v4(float4* addr, float4 v)
{
    asm volatile("red.global.add.v4.f32 [%0], {%1, %2, %3, %4};"
                 :: "l"(addr), "f"(v.x), "f"(v.y), "f"(v.z), "f"(v.w)
                 : "memory");
}

// ---------------------------------------------------------------------------
// Kernel 1: layer-1 per-node precompute (+ zero agg/cnt; + dtype detect in
// block 0). Block = 256 threads = 64 nodes x 4 feature-quads.
// ---------------------------------------------------------------------------
__global__ __launch_bounds__(256) void precompute1(
    const float* __restrict__ x,
    const float* __restrict__ W1,     // [2,48,16]
    const float* __restrict__ root1,  // [48,16]
    const float* __restrict__ b1,     // [16]
    const unsigned int* __restrict__ ei_words)
{
    __shared__ float sW0[F_IN * 16];     // quad-readable
    __shared__ float sW1[F_IN * 16];
    __shared__ float sR [F_IN * 16];
    __shared__ float sx [64 * 49];       // pitch 49: conflict-free

    int tid = threadIdx.x;

    // dtype detect (block 0, warp 0): int64 node ids < 2^31 -> odd words zero
    if (blockIdx.x == 0 && tid < 32) {
        unsigned int v = 0;
        for (int i = tid; i < 2048; i += 32) v |= ei_words[2 * i + 1];
        unsigned int any = __any_sync(0xffffffffu, v != 0u);
        if (tid == 0) g_is64 = any ? 0 : 1;
    }

    for (int i = tid; i < F_IN * 16; i += 256) {
        sW0[i] = W1[i];
        sW1[i] = W1[F_IN * 16 + i];
        sR[i]  = root1[i];
    }
    int base = blockIdx.x * 64;
    for (int i = tid; i < 64 * F_IN; i += 256)
        sx[(i / F_IN) * 49 + (i % F_IN)] = x[base * F_IN + i];
    __syncthreads();

    int nl = tid >> 2;          // node within block (0..63)
    int q  = tid & 3;           // feature quad (0..3)
    int node = base + nl;

    float4 bq = ((const float4*)b1)[q];
    float4 a0 = {0, 0, 0, 0}, a1 = {0, 0, 0, 0}, ar = bq;
    #pragma unroll
    for (int c = 0; c < F_IN; c++) {
        float xv = sx[nl * 49 + c];
        float4 w0 = ((const float4*)sW0)[c * 4 + q];
        float4 w1 = ((const float4*)sW1)[c * 4 + q];
        float4 wr = ((const float4*)sR )[c * 4 + q];
        a0.x = fmaf(xv, w0.x, a0.x); a0.y = fmaf(xv, w0.y, a0.y);
        a0.z = fmaf(xv, w0.z, a0.z); a0.w = fmaf(xv, w0.w, a0.w);
        a1.x = fmaf(xv, w1.x, a1.x); a1.y = fmaf(xv, w1.y, a1.y);
        a1.z = fmaf(xv, w1.z, a1.z); a1.w = fmaf(xv, w1.w, a1.w);
        ar.x = fmaf(xv, wr.x, ar.x); ar.y = fmaf(xv, wr.y, ar.y);
        ar.z = fmaf(xv, wr.z, ar.z); ar.w = fmaf(xv, wr.w, ar.w);
    }
    g_Y[node * 8 + q]     = a0;
    g_Y[node * 8 + 4 + q] = a1;
    g_r1[node * 4 + q] = ar;
    g_AGG[node * 4 + q] = make_float4(0.f, 0.f, 0.f, 0.f);
    if (q == 0) g_cnt[node] = 0;
}

// ---------------------------------------------------------------------------
// Kernel 2/4: edge scatter. ONE thread per edge: 3 index/attr loads,
// 8x LDG.128 gather, 4x red.global.add.v4.f32. 15 mem ops/edge.
// ---------------------------------------------------------------------------
template <int LAYER>
__global__ __launch_bounds__(256) void edge_pass(
    const void* __restrict__ ei_raw,    // [2, N_EDGES] int32 or int64
    const float* __restrict__ ea)       // [N_EDGES] (u)
{
    int e = blockIdx.x * 256 + threadIdx.x;   // grid exact: N_EDGES/256

    int src, dst;
    if (g_is64) {
        const long long* ei = (const long long*)ei_raw;
        src = (int)__ldg(&ei[e]);
        dst = (int)__ldg(&ei[N_EDGES + e]);
    } else {
        const int* ei = (const int*)ei_raw;
        src = __ldg(&ei[e]);
        dst = __ldg(&ei[N_EDGES + e]);
    }
    if ((unsigned)src >= N_NODES || (unsigned)dst >= N_NODES) return;

    float u = __ldg(&ea[e]);

    const float4* __restrict__ Y = LAYER ? g_Z : g_Y;
    float4 a0 = __ldg(&Y[src * 8 + 0]);
    float4 a1 = __ldg(&Y[src * 8 + 1]);
    float4 a2 = __ldg(&Y[src * 8 + 2]);
    float4 a3 = __ldg(&Y[src * 8 + 3]);
    float4 b0 = __ldg(&Y[src * 8 + 4]);
    float4 b1 = __ldg(&Y[src * 8 + 5]);
    float4 b2 = __ldg(&Y[src * 8 + 6]);
    float4 b3 = __ldg(&Y[src * 8 + 7]);

    float4 m0, m1, m2, m3;
    m0.x = fmaf(u, b0.x - a0.x, a0.x); m0.y = fmaf(u, b0.y - a0.y, a0.y);
    m0.z = fmaf(u, b0.z - a0.z, a0.z); m0.w = fmaf(u, b0.w - a0.w, a0.w);
    m1.x = fmaf(u, b1.x - a1.x, a1.x); m1.y = fmaf(u, b1.y - a1.y, a1.y);
    m1.z = fmaf(u, b1.z - a1.z, a1.z); m1.w = fmaf(u, b1.w - a1.w, a1.w);
    m2.x = fmaf(u, b2.x - a2.x, a2.x); m2.y = fmaf(u, b2.y - a2.y, a2.y);
    m2.z = fmaf(u, b2.z - a2.z, a2.z); m2.w = fmaf(u, b2.w - a2.w, a2.w);
    m3.x = fmaf(u, b3.x - a3.x, a3.x); m3.y = fmaf(u, b3.y - a3.y, a3.y);
    m3.z = fmaf(u, b3.z - a3.z, a3.z); m3.w = fmaf(u, b3.w - a3.w, a3.w);

    float4* agg = &g_AGG[dst * 4];
    red_add_v4(agg + 0, m0);
    red_add_v4(agg + 1, m1);
    red_add_v4(agg + 2, m2);
    red_add_v4(agg + 3, m3);
    if (LAYER == 0) atomicAdd(&g_cnt[dst], 1);
}

// ---------------------------------------------------------------------------
// Kernel 3: finalize layer 1 (mean + root + bias + ELU) fused with the
// layer-2 per-node precompute; re-zeros agg for pass 2.
// Block = 256 threads = 64 nodes x 4 quads.
// ---------------------------------------------------------------------------
__global__ __launch_bounds__(256) void mid_fused(
    const float* __restrict__ W2,     // [2,16,16]
    const float* __restrict__ root2,  // [16,16]
    const float* __restrict__ b2)     // [16]
{
    __shared__ float sW0[16 * 16];
    __shared__ float sW1[16 * 16];
    __shared__ float sR [16 * 16];
    __shared__ float sh [64 * 17];    // pitch 17: conflict-free

    int tid = threadIdx.x;
    sW0[tid] = W2[tid];
    sW1[tid] = W2[256 + tid];
    sR [tid] = root2[tid];

    int base = blockIdx.x * 64;
    int nl = tid >> 2;
    int q  = tid & 3;
    int node = base + nl;

    float cnt = fmaxf((float)g_cnt[node], 1.f);
    float inv = 1.f / cnt;
    float4 agg = g_AGG[node * 4 + q];
    float4 r1  = g_r1[node * 4 + q];
    float4 v;
    v.x = agg.x * inv + r1.x;  v.y = agg.y * inv + r1.y;
    v.z = agg.z * inv + r1.z;  v.w = agg.w * inv + r1.w;
    v.x = (v.x > 0.f) ? v.x : expm1f(v.x);
    v.y = (v.y > 0.f) ? v.y : expm1f(v.y);
    v.z = (v.z > 0.f) ? v.z : expm1f(v.z);
    v.w = (v.w > 0.f) ? v.w : expm1f(v.w);
    sh[nl * 17 + q * 4 + 0] = v.x;
    sh[nl * 17 + q * 4 + 1] = v.y;
    sh[nl * 17 + q * 4 + 2] = v.z;
    sh[nl * 17 + q * 4 + 3] = v.w;
    g_AGG[node * 4 + q] = make_float4(0.f, 0.f, 0.f, 0.f);
    __syncthreads();

    float4 bq = ((const float4*)b2)[q];
    float4 a0 = {0, 0, 0, 0}, a1 = {0, 0, 0, 0}, ar = bq;
    #pragma unroll
    for (int c = 0; c < F_HID; c++) {
        float hv = sh[nl * 17 + c];
        float4 w0 = ((const float4*)sW0)[c * 4 + q];
        float4 w1 = ((const float4*)sW1)[c * 4 + q];
        float4 wr = ((const float4*)sR )[c * 4 + q];
        a0.x = fmaf(hv, w0.x, a0.x); a0.y = fmaf(hv, w0.y, a0.y);
        a0.z = fmaf(hv, w0.z, a0.z); a0.w = fmaf(hv, w0.w, a0.w);
        a1.x = fmaf(hv, w1.x, a1.x); a1.y = fmaf(hv, w1.y, a1.y);
        a1.z = fmaf(hv, w1.z, a1.z); a1.w = fmaf(hv, w1.w, a1.w);
        ar.x = fmaf(hv, wr.x, ar.x); ar.y = fmaf(hv, wr.y, ar.y);
        ar.z = fmaf(hv, wr.z, ar.z); ar.w = fmaf(hv, wr.w, ar.w);
    }
    g_Z[node * 8 + q]     = a0;
    g_Z[node * 8 + 4 + q] = a1;
    g_r2[node * 4 + q] = ar;
}

// ---------------------------------------------------------------------------
// Kernel 5: finalize layer 2 (mean + root + bias) + log_softmax over 16.
// Thread = (node, quad); reduction = local over 4 + shfl over 2 lanes.
// ---------------------------------------------------------------------------
__global__ __launch_bounds__(256) void finalize2(float4* __restrict__ out)
{
    int idx = blockIdx.x * 256 + threadIdx.x;   // < N_NODES*4
    int node = idx >> 2;

    float cnt = fmaxf((float)g_cnt[node], 1.f);
    float inv = 1.f / cnt;
    float4 agg = g_AGG[idx];
    float4 r2  = g_r2[idx];
    float4 v;
    v.x = agg.x * inv + r2.x;  v.y = agg.y * inv + r2.y;
    v.z = agg.z * inv + r2.z;  v.w = agg.w * inv + r2.w;

    float mx = fmaxf(fmaxf(v.x, v.y), fmaxf(v.z, v.w));
    mx = fmaxf(mx, __shfl_xor_sync(0xffffffffu, mx, 1));
    mx = fmaxf(mx, __shfl_xor_sync(0xffffffffu, mx, 2));

    float s = expf(v.x - mx) + expf(v.y - mx) + expf(v.z - mx) + expf(v.w - mx);
    s += __shfl_xor_sync(0xffffffffu, s, 1);
    s += __shfl_xor_sync(0xffffffffu, s, 2);

    float c = mx + logf(s);
    float4 r;
    r.x = v.x - c; r.y = v.y - c; r.z = v.z - c; r.w = v.w - c;
    out[idx] = r;
}

// ---------------------------------------------------------------------------
extern "C" void kernel_launch(void* const* d_in, const int* in_sizes, int n_in,
                              void* d_out, int out_size)
{
    const float* x     = (const float*)d_in[0];
    const float* ea    = (const float*)d_in[1];
    const void*  ei    = d_in[2];
    const float* W1    = (const float*)d_in[3];
    const float* root1 = (const float*)d_in[4];
    const float* b1    = (const float*)d_in[5];
    const float* W2    = (const float*)d_in[6];
    const float* root2 = (const float*)d_in[7];
    const float* b2    = (const float*)d_in[8];
    float4* out = (float4*)d_out;

    const int node_blocks = (N_NODES + 63) / 64;     // 1563
    const int nq_blocks   = (N_NODES * 4 + 255) / 256;
    const int edge_blocks = N_EDGES / 256;           // 6250

    precompute1<<<node_blocks, 256>>>(x, W1, root1, b1, (const unsigned int*)ei);
    edge_pass<0><<<edge_blocks, 256>>>(ei, ea);
    mid_fused<<<node_blocks, 256>>>(W2, root2, b2);
    edge_pass<1><<<edge_blocks, 256>>>(ei, ea);
    finalize2<<<nq_blocks, 256>>>(out);
}

// round 5
// speedup vs baseline: 2.4561x; 2.4561x over previous
#include <cuda_runtime.h>

#define N_NODES 100000
#define N_EDGES 1600000
#define F_IN 48
#define F_HID 16
#define F_OUT 16

// Scratch (device globals — no allocation allowed).
// Y/Z: interleaved per-node tables, 32 floats (= 8 float4) per node:
//   float4 slots [0:4) = x @ W[0]  (a),  [4:8) = x @ W[1]  (b)
__device__ float4 g_Y[N_NODES * 8];
__device__ float4 g_Z[N_NODES * 8];
__device__ float4 g_AGG[N_NODES * 4];  // 16-float accumulator per node
__device__ float4 g_r1[N_NODES * 4];   // x @ root1 + b1
__device__ float4 g_r2[N_NODES * 4];   // h @ root2 + b2
__device__ int    g_cnt[N_NODES];      // in-degree (same both layers)
__device__ int    g_is64;              // 1 if edge_index is int64

__device__ __forceinline__ void red_add_v4(float4* addr, float4 v)
{
    asm volatile("red.global.add.v4.f32 [%0], {%1, %2, %3, %4};"
                 :: "l"(addr), "f"(v.x), "f"(v.y), "f"(v.z), "f"(v.w)
                 : "memory");
}

// ---------------------------------------------------------------------------
// Kernel 1: layer-1 per-node precompute (+ zero agg/cnt; + dtype detect in
// block 0). Block = 256 threads = 64 nodes x 4 feature-quads.
// ---------------------------------------------------------------------------
__global__ __launch_bounds__(256) void precompute1(
    const float* __restrict__ x,
    const float* __restrict__ W1,     // [2,48,16]
    const float* __restrict__ root1,  // [48,16]
    const float* __restrict__ b1,     // [16]
    const unsigned int* __restrict__ ei_words)
{
    __shared__ float sW0[F_IN * 16];
    __shared__ float sW1[F_IN * 16];
    __shared__ float sR [F_IN * 16];
    __shared__ float sx [64 * 49];       // pitch 49: conflict-free

    int tid = threadIdx.x;

    // dtype detect (block 0, warp 0): int64 node ids < 2^31 -> odd words zero
    if (blockIdx.x == 0 && tid < 32) {
        unsigned int v = 0;
        for (int i = tid; i < 2048; i += 32) v |= ei_words[2 * i + 1];
        unsigned int any = __any_sync(0xffffffffu, v != 0u);
        if (tid == 0) g_is64 = any ? 0 : 1;
    }

    for (int i = tid; i < F_IN * 16; i += 256) {
        sW0[i] = W1[i];
        sW1[i] = W1[F_IN * 16 + i];
        sR[i]  = root1[i];
    }
    int base = blockIdx.x * 64;
    for (int i = tid; i < 64 * F_IN; i += 256)
        sx[(i / F_IN) * 49 + (i % F_IN)] = x[base * F_IN + i];
    __syncthreads();

    int nl = tid >> 2;          // node within block (0..63)
    int q  = tid & 3;           // feature quad (0..3)
    int node = base + nl;

    float4 bq = ((const float4*)b1)[q];
    float4 a0 = {0, 0, 0, 0}, a1 = {0, 0, 0, 0}, ar = bq;
    #pragma unroll
    for (int c = 0; c < F_IN; c++) {
        float xv = sx[nl * 49 + c];
        float4 w0 = ((const float4*)sW0)[c * 4 + q];
        float4 w1 = ((const float4*)sW1)[c * 4 + q];
        float4 wr = ((const float4*)sR )[c * 4 + q];
        a0.x = fmaf(xv, w0.x, a0.x); a0.y = fmaf(xv, w0.y, a0.y);
        a0.z = fmaf(xv, w0.z, a0.z); a0.w = fmaf(xv, w0.w, a0.w);
        a1.x = fmaf(xv, w1.x, a1.x); a1.y = fmaf(xv, w1.y, a1.y);
        a1.z = fmaf(xv, w1.z, a1.z); a1.w = fmaf(xv, w1.w, a1.w);
        ar.x = fmaf(xv, wr.x, ar.x); ar.y = fmaf(xv, wr.y, ar.y);
        ar.z = fmaf(xv, wr.z, ar.z); ar.w = fmaf(xv, wr.w, ar.w);
    }
    g_Y[node * 8 + q]     = a0;
    g_Y[node * 8 + 4 + q] = a1;
    g_r1[node * 4 + q] = ar;
    g_AGG[node * 4 + q] = make_float4(0.f, 0.f, 0.f, 0.f);
    if (q == 0) g_cnt[node] = 0;
}

// ---------------------------------------------------------------------------
// Kernel 2/4: edge scatter. FOUR threads per edge (quad q = 4 features).
// Coalesced: 4 lanes cover one 64B span of the src node per gather instr and
// one 64B span of the dst accumulator per RED instr. (R3-proven layout.)
// ---------------------------------------------------------------------------
template <int LAYER>
__global__ __launch_bounds__(256) void edge_pass(
    const void* __restrict__ ei_raw,    // [2, N_EDGES] int32 or int64
    const float* __restrict__ ea)       // [N_EDGES] (u)
{
    int idx = blockIdx.x * 256 + threadIdx.x;   // < N_EDGES*4 = 6.4M
    int e = idx >> 2;
    int q = idx & 3;

    int src, dst;
    if (g_is64) {
        const long long* ei = (const long long*)ei_raw;
        src = (int)__ldg(&ei[e]);
        dst = (int)__ldg(&ei[N_EDGES + e]);
    } else {
        const int* ei = (const int*)ei_raw;
        src = __ldg(&ei[e]);
        dst = __ldg(&ei[N_EDGES + e]);
    }
    if ((unsigned)src >= N_NODES || (unsigned)dst >= N_NODES) return;

    float u = __ldg(&ea[e]);

    const float4* __restrict__ Y = LAYER ? g_Z : g_Y;
    float4 a = __ldg(&Y[src * 8 + q]);
    float4 b = __ldg(&Y[src * 8 + 4 + q]);

    float4 m;
    m.x = fmaf(u, b.x - a.x, a.x);
    m.y = fmaf(u, b.y - a.y, a.y);
    m.z = fmaf(u, b.z - a.z, a.z);
    m.w = fmaf(u, b.w - a.w, a.w);

    red_add_v4(&g_AGG[dst * 4 + q], m);
    if (LAYER == 0 && q == 0) atomicAdd(&g_cnt[dst], 1);
}

// ---------------------------------------------------------------------------
// Kernel 3: finalize layer 1 (mean + root + bias + ELU) fused with the
// layer-2 per-node precompute; re-zeros agg for pass 2.
// Block = 256 threads = 64 nodes x 4 quads.
// ---------------------------------------------------------------------------
__global__ __launch_bounds__(256) void mid_fused(
    const float* __restrict__ W2,     // [2,16,16]
    const float* __restrict__ root2,  // [16,16]
    const float* __restrict__ b2)     // [16]
{
    __shared__ float sW0[16 * 16];
    __shared__ float sW1[16 * 16];
    __shared__ float sR [16 * 16];
    __shared__ float sh [64 * 17];    // pitch 17: conflict-free

    int tid = threadIdx.x;
    sW0[tid] = W2[tid];
    sW1[tid] = W2[256 + tid];
    sR [tid] = root2[tid];

    int base = blockIdx.x * 64;
    int nl = tid >> 2;
    int q  = tid & 3;
    int node = base + nl;

    float cnt = fmaxf((float)g_cnt[node], 1.f);
    float inv = 1.f / cnt;
    float4 agg = g_AGG[node * 4 + q];
    float4 r1  = g_r1[node * 4 + q];
    float4 v;
    v.x = agg.x * inv + r1.x;  v.y = agg.y * inv + r1.y;
    v.z = agg.z * inv + r1.z;  v.w = agg.w * inv + r1.w;
    v.x = (v.x > 0.f) ? v.x : expm1f(v.x);
    v.y = (v.y > 0.f) ? v.y : expm1f(v.y);
    v.z = (v.z > 0.f) ? v.z : expm1f(v.z);
    v.w = (v.w > 0.f) ? v.w : expm1f(v.w);
    sh[nl * 17 + q * 4 + 0] = v.x;
    sh[nl * 17 + q * 4 + 1] = v.y;
    sh[nl * 17 + q * 4 + 2] = v.z;
    sh[nl * 17 + q * 4 + 3] = v.w;
    g_AGG[node * 4 + q] = make_float4(0.f, 0.f, 0.f, 0.f);
    __syncthreads();

    float4 bq = ((const float4*)b2)[q];
    float4 a0 = {0, 0, 0, 0}, a1 = {0, 0, 0, 0}, ar = bq;
    #pragma unroll
    for (int c = 0; c < F_HID; c++) {
        float hv = sh[nl * 17 + c];
        float4 w0 = ((const float4*)sW0)[c * 4 + q];
        float4 w1 = ((const float4*)sW1)[c * 4 + q];
        float4 wr = ((const float4*)sR )[c * 4 + q];
        a0.x = fmaf(hv, w0.x, a0.x); a0.y = fmaf(hv, w0.y, a0.y);
        a0.z = fmaf(hv, w0.z, a0.z); a0.w = fmaf(hv, w0.w, a0.w);
        a1.x = fmaf(hv, w1.x, a1.x); a1.y = fmaf(hv, w1.y, a1.y);
        a1.z = fmaf(hv, w1.z, a1.z); a1.w = fmaf(hv, w1.w, a1.w);
        ar.x = fmaf(hv, wr.x, ar.x); ar.y = fmaf(hv, wr.y, ar.y);
        ar.z = fmaf(hv, wr.z, ar.z); ar.w = fmaf(hv, wr.w, ar.w);
    }
    g_Z[node * 8 + q]     = a0;
    g_Z[node * 8 + 4 + q] = a1;
    g_r2[node * 4 + q] = ar;
}

// ---------------------------------------------------------------------------
// Kernel 5: finalize layer 2 (mean + root + bias) + log_softmax over 16.
// Thread = (node, quad); reduction = local over 4 + shfl over 2 lanes.
// ---------------------------------------------------------------------------
__global__ __launch_bounds__(256) void finalize2(float4* __restrict__ out)
{
    int idx = blockIdx.x * 256 + threadIdx.x;   // < N_NODES*4
    int node = idx >> 2;

    float cnt = fmaxf((float)g_cnt[node], 1.f);
    float inv = 1.f / cnt;
    float4 agg = g_AGG[idx];
    float4 r2  = g_r2[idx];
    float4 v;
    v.x = agg.x * inv + r2.x;  v.y = agg.y * inv + r2.y;
    v.z = agg.z * inv + r2.z;  v.w = agg.w * inv + r2.w;

    float mx = fmaxf(fmaxf(v.x, v.y), fmaxf(v.z, v.w));
    mx = fmaxf(mx, __shfl_xor_sync(0xffffffffu, mx, 1));
    mx = fmaxf(mx, __shfl_xor_sync(0xffffffffu, mx, 2));

    float s = expf(v.x - mx) + expf(v.y - mx) + expf(v.z - mx) + expf(v.w - mx);
    s += __shfl_xor_sync(0xffffffffu, s, 1);
    s += __shfl_xor_sync(0xffffffffu, s, 2);

    float c = mx + logf(s);
    float4 r;
    r.x = v.x - c; r.y = v.y - c; r.z = v.z - c; r.w = v.w - c;
    out[idx] = r;
}

// ---------------------------------------------------------------------------
extern "C" void kernel_launch(void* const* d_in, const int* in_sizes, int n_in,
                              void* d_out, int out_size)
{
    const float* x     = (const float*)d_in[0];
    const float* ea    = (const float*)d_in[1];
    const void*  ei    = d_in[2];
    const float* W1    = (const float*)d_in[3];
    const float* root1 = (const float*)d_in[4];
    const float* b1    = (const float*)d_in[5];
    const float* W2    = (const float*)d_in[6];
    const float* root2 = (const float*)d_in[7];
    const float* b2    = (const float*)d_in[8];
    float4* out = (float4*)d_out;

    const int node_blocks = (N_NODES + 63) / 64;     // 1563
    const int nq_blocks   = (N_NODES * 4 + 255) / 256;
    const int edge_blocks = (N_EDGES * 4) / 256;     // 25000

    precompute1<<<node_blocks, 256>>>(x, W1, root1, b1, (const unsigned int*)ei);
    edge_pass<0><<<edge_blocks, 256>>>(ei, ea);
    mid_fused<<<node_blocks, 256>>>(W2, root2, b2);
    edge_pass<1><<<edge_blocks, 256>>>(ei, ea);
    finalize2<<<nq_blocks, 256>>>(out);
}

// round 6
// speedup vs baseline: 2.5794x; 1.0502x over previous
#include <cuda_runtime.h>

#define N_NODES 100000
#define N_EDGES 1600000
#define F_IN 48
#define F_HID 16
#define F_OUT 16

// Scratch (device globals — no allocation allowed).
// Y/Z: interleaved per-node tables, 32 floats (= 8 float4) per node:
//   float4 slots [0:4) = x @ W[0]  (a),  [4:8) = x @ W[1]  (b)
__device__ float4 g_Y[N_NODES * 8];
__device__ float4 g_Z[N_NODES * 8];
__device__ float4 g_AGG[N_NODES * 4];  // 16-float accumulator per node
__device__ float4 g_r1[N_NODES * 4];   // x @ root1 + b1
__device__ float4 g_r2[N_NODES * 4];   // h @ root2 + b2
__device__ int    g_cnt[N_NODES];      // in-degree (same both layers)
__device__ int    g_is64;              // 1 if edge_index is int64

__device__ __forceinline__ void red_add_v4(float4* addr, float4 v)
{
    asm volatile("red.global.add.v4.f32 [%0], {%1, %2, %3, %4};"
                 :: "l"(addr), "f"(v.x), "f"(v.y), "f"(v.z), "f"(v.w)
                 : "memory");
}

// ---------------------------------------------------------------------------
// Kernel 1: layer-1 per-node precompute (+ zero agg/cnt; + dtype detect in
// block 0). Block = 256 threads = 64 nodes x 4 feature-quads.
// ---------------------------------------------------------------------------
__global__ __launch_bounds__(256) void precompute1(
    const float* __restrict__ x,
    const float* __restrict__ W1,     // [2,48,16]
    const float* __restrict__ root1,  // [48,16]
    const float* __restrict__ b1,     // [16]
    const unsigned int* __restrict__ ei_words)
{
    __shared__ float sW0[F_IN * 16];
    __shared__ float sW1[F_IN * 16];
    __shared__ float sR [F_IN * 16];
    __shared__ float sx [64 * 49];       // pitch 49: conflict-free

    int tid = threadIdx.x;

    // dtype detect (block 0, warp 0): int64 node ids < 2^31 -> odd words zero
    if (blockIdx.x == 0 && tid < 32) {
        unsigned int v = 0;
        for (int i = tid; i < 2048; i += 32) v |= ei_words[2 * i + 1];
        unsigned int any = __any_sync(0xffffffffu, v != 0u);
        if (tid == 0) g_is64 = any ? 0 : 1;
    }

    for (int i = tid; i < F_IN * 16; i += 256) {
        sW0[i] = W1[i];
        sW1[i] = W1[F_IN * 16 + i];
        sR[i]  = root1[i];
    }
    int base = blockIdx.x * 64;
    for (int i = tid; i < 64 * F_IN; i += 256)
        sx[(i / F_IN) * 49 + (i % F_IN)] = x[base * F_IN + i];
    __syncthreads();

    int nl = tid >> 2;          // node within block (0..63)
    int q  = tid & 3;           // feature quad (0..3)
    int node = base + nl;

    float4 bq = ((const float4*)b1)[q];
    float4 a0 = {0, 0, 0, 0}, a1 = {0, 0, 0, 0}, ar = bq;
    #pragma unroll
    for (int c = 0; c < F_IN; c++) {
        float xv = sx[nl * 49 + c];
        float4 w0 = ((const float4*)sW0)[c * 4 + q];
        float4 w1 = ((const float4*)sW1)[c * 4 + q];
        float4 wr = ((const float4*)sR )[c * 4 + q];
        a0.x = fmaf(xv, w0.x, a0.x); a0.y = fmaf(xv, w0.y, a0.y);
        a0.z = fmaf(xv, w0.z, a0.z); a0.w = fmaf(xv, w0.w, a0.w);
        a1.x = fmaf(xv, w1.x, a1.x); a1.y = fmaf(xv, w1.y, a1.y);
        a1.z = fmaf(xv, w1.z, a1.z); a1.w = fmaf(xv, w1.w, a1.w);
        ar.x = fmaf(xv, wr.x, ar.x); ar.y = fmaf(xv, wr.y, ar.y);
        ar.z = fmaf(xv, wr.z, ar.z); ar.w = fmaf(xv, wr.w, ar.w);
    }
    g_Y[node * 8 + q]     = a0;
    g_Y[node * 8 + 4 + q] = a1;
    g_r1[node * 4 + q] = ar;
    g_AGG[node * 4 + q] = make_float4(0.f, 0.f, 0.f, 0.f);
    if (q == 0) g_cnt[node] = 0;
}

// ---------------------------------------------------------------------------
// Kernel 2/4: edge scatter. Each 4-lane quad handles TWO consecutive edges
// (doubled MLP: 2 index loads + 4 gathers all independent). Per edge the 4
// lanes cover one 64B span per memory instruction (R3/R5-proven coalescing).
// ---------------------------------------------------------------------------
template <int LAYER>
__global__ __launch_bounds__(256) void edge_pass(
    const void* __restrict__ ei_raw,    // [2, N_EDGES] int32 or int64
    const float* __restrict__ ea)       // [N_EDGES] (u)
{
    int idx = blockIdx.x * 256 + threadIdx.x;   // < N_EDGES*2
    int p = idx >> 2;                           // edge pair index
    int q = idx & 3;                            // feature quad
    int e0 = 2 * p;
    int e1 = 2 * p + 1;

    int src0, dst0, src1, dst1;
    if (g_is64) {
        const long long* ei = (const long long*)ei_raw;
        src0 = (int)__ldg(&ei[e0]);
        src1 = (int)__ldg(&ei[e1]);
        dst0 = (int)__ldg(&ei[N_EDGES + e0]);
        dst1 = (int)__ldg(&ei[N_EDGES + e1]);
    } else {
        const int* ei = (const int*)ei_raw;
        src0 = __ldg(&ei[e0]);
        src1 = __ldg(&ei[e1]);
        dst0 = __ldg(&ei[N_EDGES + e0]);
        dst1 = __ldg(&ei[N_EDGES + e1]);
    }
    float u0 = __ldg(&ea[e0]);
    float u1 = __ldg(&ea[e1]);

    bool ok0 = (unsigned)src0 < N_NODES && (unsigned)dst0 < N_NODES;
    bool ok1 = (unsigned)src1 < N_NODES && (unsigned)dst1 < N_NODES;

    const float4* __restrict__ Y = LAYER ? g_Z : g_Y;

    if (ok0) {
        float4 a = __ldg(&Y[src0 * 8 + q]);
        float4 b = __ldg(&Y[src0 * 8 + 4 + q]);
        float4 m;
        m.x = fmaf(u0, b.x - a.x, a.x);
        m.y = fmaf(u0, b.y - a.y, a.y);
        m.z = fmaf(u0, b.z - a.z, a.z);
        m.w = fmaf(u0, b.w - a.w, a.w);
        red_add_v4(&g_AGG[dst0 * 4 + q], m);
        if (LAYER == 0 && q == 0) atomicAdd(&g_cnt[dst0], 1);
    }
    if (ok1) {
        float4 a = __ldg(&Y[src1 * 8 + q]);
        float4 b = __ldg(&Y[src1 * 8 + 4 + q]);
        float4 m;
        m.x = fmaf(u1, b.x - a.x, a.x);
        m.y = fmaf(u1, b.y - a.y, a.y);
        m.z = fmaf(u1, b.z - a.z, a.z);
        m.w = fmaf(u1, b.w - a.w, a.w);
        red_add_v4(&g_AGG[dst1 * 4 + q], m);
        if (LAYER == 0 && q == 0) atomicAdd(&g_cnt[dst1], 1);
    }
}

// ---------------------------------------------------------------------------
// Kernel 3: finalize layer 1 (mean + root + bias + ELU) fused with the
// layer-2 per-node precompute; re-zeros agg for pass 2.
// Block = 256 threads = 64 nodes x 4 quads.
// ---------------------------------------------------------------------------
__global__ __launch_bounds__(256) void mid_fused(
    const float* __restrict__ W2,     // [2,16,16]
    const float* __restrict__ root2,  // [16,16]
    const float* __restrict__ b2)     // [16]
{
    __shared__ float sW0[16 * 16];
    __shared__ float sW1[16 * 16];
    __shared__ float sR [16 * 16];
    __shared__ float sh [64 * 17];    // pitch 17: conflict-free

    int tid = threadIdx.x;
    sW0[tid] = W2[tid];
    sW1[tid] = W2[256 + tid];
    sR [tid] = root2[tid];

    int base = blockIdx.x * 64;
    int nl = tid >> 2;
    int q  = tid & 3;
    int node = base + nl;

    float cnt = fmaxf((float)g_cnt[node], 1.f);
    float inv = 1.f / cnt;
    float4 agg = g_AGG[node * 4 + q];
    float4 r1  = g_r1[node * 4 + q];
    float4 v;
    v.x = agg.x * inv + r1.x;  v.y = agg.y * inv + r1.y;
    v.z = agg.z * inv + r1.z;  v.w = agg.w * inv + r1.w;
    v.x = (v.x > 0.f) ? v.x : expm1f(v.x);
    v.y = (v.y > 0.f) ? v.y : expm1f(v.y);
    v.z = (v.z > 0.f) ? v.z : expm1f(v.z);
    v.w = (v.w > 0.f) ? v.w : expm1f(v.w);
    sh[nl * 17 + q * 4 + 0] = v.x;
    sh[nl * 17 + q * 4 + 1] = v.y;
    sh[nl * 17 + q * 4 + 2] = v.z;
    sh[nl * 17 + q * 4 + 3] = v.w;
    g_AGG[node * 4 + q] = make_float4(0.f, 0.f, 0.f, 0.f);
    __syncthreads();

    float4 bq = ((const float4*)b2)[q];
    float4 a0 = {0, 0, 0, 0}, a1 = {0, 0, 0, 0}, ar = bq;
    #pragma unroll
    for (int c = 0; c < F_HID; c++) {
        float hv = sh[nl * 17 + c];
        float4 w0 = ((const float4*)sW0)[c * 4 + q];
        float4 w1 = ((const float4*)sW1)[c * 4 + q];
        float4 wr = ((const float4*)sR )[c * 4 + q];
        a0.x = fmaf(hv, w0.x, a0.x); a0.y = fmaf(hv, w0.y, a0.y);
        a0.z = fmaf(hv, w0.z, a0.z); a0.w = fmaf(hv, w0.w, a0.w);
        a1.x = fmaf(hv, w1.x, a1.x); a1.y = fmaf(hv, w1.y, a1.y);
        a1.z = fmaf(hv, w1.z, a1.z); a1.w = fmaf(hv, w1.w, a1.w);
        ar.x = fmaf(hv, wr.x, ar.x); ar.y = fmaf(hv, wr.y, ar.y);
        ar.z = fmaf(hv, wr.z, ar.z); ar.w = fmaf(hv, wr.w, ar.w);
    }
    g_Z[node * 8 + q]     = a0;
    g_Z[node * 8 + 4 + q] = a1;
    g_r2[node * 4 + q] = ar;
}

// ---------------------------------------------------------------------------
// Kernel 5: finalize layer 2 (mean + root + bias) + log_softmax over 16.
// Thread = (node, quad); reduction = local over 4 + shfl over 2 lanes.
// ---------------------------------------------------------------------------
__global__ __launch_bounds__(256) void finalize2(float4* __restrict__ out)
{
    int idx = blockIdx.x * 256 + threadIdx.x;   // < N_NODES*4
    int node = idx >> 2;

    float cnt = fmaxf((float)g_cnt[node], 1.f);
    float inv = 1.f / cnt;
    float4 agg = g_AGG[idx];
    float4 r2  = g_r2[idx];
    float4 v;
    v.x = agg.x * inv + r2.x;  v.y = agg.y * inv + r2.y;
    v.z = agg.z * inv + r2.z;  v.w = agg.w * inv + r2.w;

    float mx = fmaxf(fmaxf(v.x, v.y), fmaxf(v.z, v.w));
    mx = fmaxf(mx, __shfl_xor_sync(0xffffffffu, mx, 1));
    mx = fmaxf(mx, __shfl_xor_sync(0xffffffffu, mx, 2));

    float s = expf(v.x - mx) + expf(v.y - mx) + expf(v.z - mx) + expf(v.w - mx);
    s += __shfl_xor_sync(0xffffffffu, s, 1);
    s += __shfl_xor_sync(0xffffffffu, s, 2);

    float c = mx + logf(s);
    float4 r;
    r.x = v.x - c; r.y = v.y - c; r.z = v.z - c; r.w = v.w - c;
    out[idx] = r;
}

// ---------------------------------------------------------------------------
extern "C" void kernel_launch(void* const* d_in, const int* in_sizes, int n_in,
                              void* d_out, int out_size)
{
    const float* x     = (const float*)d_in[0];
    const float* ea    = (const float*)d_in[1];
    const void*  ei    = d_in[2];
    const float* W1    = (const float*)d_in[3];
    const float* root1 = (const float*)d_in[4];
    const float* b1    = (const float*)d_in[5];
    const float* W2    = (const float*)d_in[6];
    const float* root2 = (const float*)d_in[7];
    const float* b2    = (const float*)d_in[8];
    float4* out = (float4*)d_out;

    const int node_blocks = (N_NODES + 63) / 64;     // 1563
    const int nq_blocks   = (N_NODES * 4 + 255) / 256;
    const int edge_blocks = (N_EDGES * 2) / 256;     // 12500

    precompute1<<<node_blocks, 256>>>(x, W1, root1, b1, (const unsigned int*)ei);
    edge_pass<0><<<edge_blocks, 256>>>(ei, ea);
    mid_fused<<<node_blocks, 256>>>(W2, root2, b2);
    edge_pass<1><<<edge_blocks, 256>>>(ei, ea);
    finalize2<<<nq_blocks, 256>>>(out);
}

// round 7
// speedup vs baseline: 2.8329x; 1.0983x over previous
#include <cuda_runtime.h>
#include <cuda_fp16.h>

#define N_NODES 100000
#define N_EDGES 1600000
#define F_IN 48
#define F_HID 16
#define F_OUT 16

// Scratch (device globals — no allocation allowed).
// Yh/Zh: fp16 per-node tables, 32 halves (64B) per node as 8x uint2:
//   uint2 slots [0:4) = x @ W[0] (a, 16 halves), [4:8) = x @ W[1] (b)
__device__ uint2  g_Yh[N_NODES * 8];
__device__ uint2  g_Zh[N_NODES * 8];
__device__ float4 g_AGG[N_NODES * 4];  // 16-float fp32 accumulator per node
__device__ float4 g_r1[N_NODES * 4];   // x @ root1 + b1 (fp32)
__device__ float4 g_r2[N_NODES * 4];   // h @ root2 + b2 (fp32)
__device__ int    g_cnt[N_NODES];      // in-degree (same both layers)
__device__ int    g_is64;              // 1 if edge_index is int64

__device__ __forceinline__ void red_add_v4(float4* addr, float4 v)
{
    asm volatile("red.global.add.v4.f32 [%0], {%1, %2, %3, %4};"
                 :: "l"(addr), "f"(v.x), "f"(v.y), "f"(v.z), "f"(v.w)
                 : "memory");
}

__device__ __forceinline__ unsigned pack_h2(float lo, float hi)
{
    __half2 h = __floats2half2_rn(lo, hi);
    return *reinterpret_cast<unsigned*>(&h);
}
__device__ __forceinline__ float2 unpack_h2(unsigned u)
{
    __half2 h = *reinterpret_cast<__half2*>(&u);
    return __half22float2(h);
}

// ---------------------------------------------------------------------------
// Kernel 1: layer-1 per-node precompute (+ zero agg/cnt; + dtype detect in
// block 0). Block = 256 threads = 64 nodes x 4 feature-quads.
// ---------------------------------------------------------------------------
__global__ __launch_bounds__(256) void precompute1(
    const float* __restrict__ x,
    const float* __restrict__ W1,     // [2,48,16]
    const float* __restrict__ root1,  // [48,16]
    const float* __restrict__ b1,     // [16]
    const unsigned int* __restrict__ ei_words)
{
    __shared__ float sW0[F_IN * 16];
    __shared__ float sW1[F_IN * 16];
    __shared__ float sR [F_IN * 16];
    __shared__ float sx [64 * 49];       // pitch 49: conflict-free

    int tid = threadIdx.x;

    // dtype detect (block 0, warp 0): int64 node ids < 2^31 -> odd words zero
    if (blockIdx.x == 0 && tid < 32) {
        unsigned int v = 0;
        for (int i = tid; i < 2048; i += 32) v |= ei_words[2 * i + 1];
        unsigned int any = __any_sync(0xffffffffu, v != 0u);
        if (tid == 0) g_is64 = any ? 0 : 1;
    }

    for (int i = tid; i < F_IN * 16; i += 256) {
        sW0[i] = W1[i];
        sW1[i] = W1[F_IN * 16 + i];
        sR[i]  = root1[i];
    }
    int base = blockIdx.x * 64;
    for (int i = tid; i < 64 * F_IN; i += 256)
        sx[(i / F_IN) * 49 + (i % F_IN)] = x[base * F_IN + i];
    __syncthreads();

    int nl = tid >> 2;          // node within block (0..63)
    int q  = tid & 3;           // feature quad (0..3)
    int node = base + nl;

    float4 bq = ((const float4*)b1)[q];
    float4 a0 = {0, 0, 0, 0}, a1 = {0, 0, 0, 0}, ar = bq;
    #pragma unroll
    for (int c = 0; c < F_IN; c++) {
        float xv = sx[nl * 49 + c];
        float4 w0 = ((const float4*)sW0)[c * 4 + q];
        float4 w1 = ((const float4*)sW1)[c * 4 + q];
        float4 wr = ((const float4*)sR )[c * 4 + q];
        a0.x = fmaf(xv, w0.x, a0.x); a0.y = fmaf(xv, w0.y, a0.y);
        a0.z = fmaf(xv, w0.z, a0.z); a0.w = fmaf(xv, w0.w, a0.w);
        a1.x = fmaf(xv, w1.x, a1.x); a1.y = fmaf(xv, w1.y, a1.y);
        a1.z = fmaf(xv, w1.z, a1.z); a1.w = fmaf(xv, w1.w, a1.w);
        ar.x = fmaf(xv, wr.x, ar.x); ar.y = fmaf(xv, wr.y, ar.y);
        ar.z = fmaf(xv, wr.z, ar.z); ar.w = fmaf(xv, wr.w, ar.w);
    }
    g_Yh[node * 8 + q]     = make_uint2(pack_h2(a0.x, a0.y), pack_h2(a0.z, a0.w));
    g_Yh[node * 8 + 4 + q] = make_uint2(pack_h2(a1.x, a1.y), pack_h2(a1.z, a1.w));
    g_r1[node * 4 + q] = ar;
    g_AGG[node * 4 + q] = make_float4(0.f, 0.f, 0.f, 0.f);
    if (q == 0) g_cnt[node] = 0;
}

// ---------------------------------------------------------------------------
// Kernel 2/4: edge scatter. Each 4-lane quad handles TWO consecutive edges.
// fp16 gathers (LDG.64 per quad per operand) halve L2 traffic vs fp32;
// math + RED accumulation stay fp32.
// ---------------------------------------------------------------------------
template <int LAYER>
__global__ __launch_bounds__(256) void edge_pass(
    const void* __restrict__ ei_raw,    // [2, N_EDGES] int32 or int64
    const float* __restrict__ ea)       // [N_EDGES] (u)
{
    int idx = blockIdx.x * 256 + threadIdx.x;   // < N_EDGES*2
    int p = idx >> 2;                           // edge pair index
    int q = idx & 3;                            // feature quad
    int e0 = 2 * p;
    int e1 = 2 * p + 1;

    int src0, dst0, src1, dst1;
    if (g_is64) {
        const long long* ei = (const long long*)ei_raw;
        src0 = (int)__ldg(&ei[e0]);
        src1 = (int)__ldg(&ei[e1]);
        dst0 = (int)__ldg(&ei[N_EDGES + e0]);
        dst1 = (int)__ldg(&ei[N_EDGES + e1]);
    } else {
        const int* ei = (const int*)ei_raw;
        src0 = __ldg(&ei[e0]);
        src1 = __ldg(&ei[e1]);
        dst0 = __ldg(&ei[N_EDGES + e0]);
        dst1 = __ldg(&ei[N_EDGES + e1]);
    }
    float u0 = __ldg(&ea[e0]);
    float u1 = __ldg(&ea[e1]);

    bool ok0 = (unsigned)src0 < N_NODES && (unsigned)dst0 < N_NODES;
    bool ok1 = (unsigned)src1 < N_NODES && (unsigned)dst1 < N_NODES;

    const uint2* __restrict__ Y = LAYER ? g_Zh : g_Yh;

    if (ok0) {
        uint2 ua = __ldg(&Y[src0 * 8 + q]);
        uint2 ub = __ldg(&Y[src0 * 8 + 4 + q]);
        float2 a01 = unpack_h2(ua.x), a23 = unpack_h2(ua.y);
        float2 b01 = unpack_h2(ub.x), b23 = unpack_h2(ub.y);
        float4 m;
        m.x = fmaf(u0, b01.x - a01.x, a01.x);
        m.y = fmaf(u0, b01.y - a01.y, a01.y);
        m.z = fmaf(u0, b23.x - a23.x, a23.x);
        m.w = fmaf(u0, b23.y - a23.y, a23.y);
        red_add_v4(&g_AGG[dst0 * 4 + q], m);
        if (LAYER == 0 && q == 0) atomicAdd(&g_cnt[dst0], 1);
    }
    if (ok1) {
        uint2 ua = __ldg(&Y[src1 * 8 + q]);
        uint2 ub = __ldg(&Y[src1 * 8 + 4 + q]);
        float2 a01 = unpack_h2(ua.x), a23 = unpack_h2(ua.y);
        float2 b01 = unpack_h2(ub.x), b23 = unpack_h2(ub.y);
        float4 m;
        m.x = fmaf(u1, b01.x - a01.x, a01.x);
        m.y = fmaf(u1, b01.y - a01.y, a01.y);
        m.z = fmaf(u1, b23.x - a23.x, a23.x);
        m.w = fmaf(u1, b23.y - a23.y, a23.y);
        red_add_v4(&g_AGG[dst1 * 4 + q], m);
        if (LAYER == 0 && q == 0) atomicAdd(&g_cnt[dst1], 1);
    }
}

// ---------------------------------------------------------------------------
// Kernel 3: finalize layer 1 (mean + root + bias + ELU) fused with the
// layer-2 per-node precompute; re-zeros agg for pass 2.
// Block = 256 threads = 64 nodes x 4 quads.
// ---------------------------------------------------------------------------
__global__ __launch_bounds__(256) void mid_fused(
    const float* __restrict__ W2,     // [2,16,16]
    const float* __restrict__ root2,  // [16,16]
    const float* __restrict__ b2)     // [16]
{
    __shared__ float sW0[16 * 16];
    __shared__ float sW1[16 * 16];
    __shared__ float sR [16 * 16];
    __shared__ float sh [64 * 17];    // pitch 17: conflict-free

    int tid = threadIdx.x;
    sW0[tid] = W2[tid];
    sW1[tid] = W2[256 + tid];
    sR [tid] = root2[tid];

    int base = blockIdx.x * 64;
    int nl = tid >> 2;
    int q  = tid & 3;
    int node = base + nl;

    float cnt = fmaxf((float)g_cnt[node], 1.f);
    float inv = 1.f / cnt;
    float4 agg = g_AGG[node * 4 + q];
    float4 r1  = g_r1[node * 4 + q];
    float4 v;
    v.x = agg.x * inv + r1.x;  v.y = agg.y * inv + r1.y;
    v.z = agg.z * inv + r1.z;  v.w = agg.w * inv + r1.w;
    v.x = (v.x > 0.f) ? v.x : expm1f(v.x);
    v.y = (v.y > 0.f) ? v.y : expm1f(v.y);
    v.z = (v.z > 0.f) ? v.z : expm1f(v.z);
    v.w = (v.w > 0.f) ? v.w : expm1f(v.w);
    sh[nl * 17 + q * 4 + 0] = v.x;
    sh[nl * 17 + q * 4 + 1] = v.y;
    sh[nl * 17 + q * 4 + 2] = v.z;
    sh[nl * 17 + q * 4 + 3] = v.w;
    g_AGG[node * 4 + q] = make_float4(0.f, 0.f, 0.f, 0.f);
    __syncthreads();

    float4 bq = ((const float4*)b2)[q];
    float4 a0 = {0, 0, 0, 0}, a1 = {0, 0, 0, 0}, ar = bq;
    #pragma unroll
    for (int c = 0; c < F_HID; c++) {
        float hv = sh[nl * 17 + c];
        float4 w0 = ((const float4*)sW0)[c * 4 + q];
        float4 w1 = ((const float4*)sW1)[c * 4 + q];
        float4 wr = ((const float4*)sR )[c * 4 + q];
        a0.x = fmaf(hv, w0.x, a0.x); a0.y = fmaf(hv, w0.y, a0.y);
        a0.z = fmaf(hv, w0.z, a0.z); a0.w = fmaf(hv, w0.w, a0.w);
        a1.x = fmaf(hv, w1.x, a1.x); a1.y = fmaf(hv, w1.y, a1.y);
        a1.z = fmaf(hv, w1.z, a1.z); a1.w = fmaf(hv, w1.w, a1.w);
        ar.x = fmaf(hv, wr.x, ar.x); ar.y = fmaf(hv, wr.y, ar.y);
        ar.z = fmaf(hv, wr.z, ar.z); ar.w = fmaf(hv, wr.w, ar.w);
    }
    g_Zh[node * 8 + q]     = make_uint2(pack_h2(a0.x, a0.y), pack_h2(a0.z, a0.w));
    g_Zh[node * 8 + 4 + q] = make_uint2(pack_h2(a1.x, a1.y), pack_h2(a1.z, a1.w));
    g_r2[node * 4 + q] = ar;
}

// ---------------------------------------------------------------------------
// Kernel 5: finalize layer 2 (mean + root + bias) + log_softmax over 16.
// Thread = (node, quad); reduction = local over 4 + shfl over 2 lanes.
// ---------------------------------------------------------------------------
__global__ __launch_bounds__(256) void finalize2(float4* __restrict__ out)
{
    int idx = blockIdx.x * 256 + threadIdx.x;   // < N_NODES*4
    int node = idx >> 2;

    float cnt = fmaxf((float)g_cnt[node], 1.f);
    float inv = 1.f / cnt;
    float4 agg = g_AGG[idx];
    float4 r2  = g_r2[idx];
    float4 v;
    v.x = agg.x * inv + r2.x;  v.y = agg.y * inv + r2.y;
    v.z = agg.z * inv + r2.z;  v.w = agg.w * inv + r2.w;

    float mx = fmaxf(fmaxf(v.x, v.y), fmaxf(v.z, v.w));
    mx = fmaxf(mx, __shfl_xor_sync(0xffffffffu, mx, 1));
    mx = fmaxf(mx, __shfl_xor_sync(0xffffffffu, mx, 2));

    float s = expf(v.x - mx) + expf(v.y - mx) + expf(v.z - mx) + expf(v.w - mx);
    s += __shfl_xor_sync(0xffffffffu, s, 1);
    s += __shfl_xor_sync(0xffffffffu, s, 2);

    float c = mx + logf(s);
    float4 r;
    r.x = v.x - c; r.y = v.y - c; r.z = v.z - c; r.w = v.w - c;
    out[idx] = r;
}

// ---------------------------------------------------------------------------
extern "C" void kernel_launch(void* const* d_in, const int* in_sizes, int n_in,
                              void* d_out, int out_size)
{
    const float* x     = (const float*)d_in[0];
    const float* ea    = (const float*)d_in[1];
    const void*  ei    = d_in[2];
    const float* W1    = (const float*)d_in[3];
    const float* root1 = (const float*)d_in[4];
    const float* b1    = (const float*)d_in[5];
    const float* W2    = (const float*)d_in[6];
    const float* root2 = (const float*)d_in[7];
    const float* b2    = (const float*)d_in[8];
    float4* out = (float4*)d_out;

    const int node_blocks = (N_NODES + 63) / 64;     // 1563
    const int nq_blocks   = (N_NODES * 4 + 255) / 256;
    const int edge_blocks = (N_EDGES * 2) / 256;     // 12500

    precompute1<<<node_blocks, 256>>>(x, W1, root1, b1, (const unsigned int*)ei);
    edge_pass<0><<<edge_blocks, 256>>>(ei, ea);
    mid_fused<<<node_blocks, 256>>>(W2, root2, b2);
    edge_pass<1><<<edge_blocks, 256>>>(ei, ea);
    finalize2<<<nq_blocks, 256>>>(out);
}